// round 6
// baseline (speedup 1.0000x reference)
#include <cuda_runtime.h>
#include <cstdint>
#include <math.h>

#define EPSV 1e-5f
static const long long CNE = (long long)512 * 4096;
static const long long NNE = (long long)4096 * 4096;
static const long long WWE = (long long)512 * 512;
static const long long QKB = (long long)4096 * 1024;
static const long long CCB = (long long)512 * 512;

// ---------------- scratch (device globals; no runtime allocation) ----------------
__device__ float g_ct  [(size_t)4 * 4096 * 512];
__device__ float g_st  [(size_t)4 * 4096 * 512];
__device__ float g_xnt [(size_t)4 * 4096 * 512];
__device__ float g_qkt [(size_t)4 * 4096 * 1024];
__device__ float g_v   [(size_t)4 * 512 * 4096];
__device__ float g_fg  [(size_t)4 * 1024 * 4096];
__device__ float g_ht  [(size_t)4 * 4096 * 512];
__device__ float g_ot  [(size_t)4 * 4096 * 512];
__device__ float g_cft [(size_t)4 * 4096 * 512];
__device__ float g_sft [(size_t)4 * 4096 * 512];
__device__ float g_attn[(size_t)4 * 4096 * 4096];
__device__ float g_attnT[(size_t)4 * 512 * 512];
__device__ float g_part[(size_t)4 * 16 * 512 * 2];
__device__ float2 g_minv[(size_t)4 * 512];

// ---------------- input transpose: [C][N] -> [N][C] ----------------
__global__ void transp_kernel(const float* __restrict__ x, float* __restrict__ xt) {
    __shared__ float t[32][33];
    int b = blockIdx.z;
    const float* xb = x + (size_t)b * CNE;
    float* xtb = xt + (size_t)b * CNE;
    int s0 = blockIdx.x * 32, c0 = blockIdx.y * 32;
    int tx = threadIdx.x & 31, ty = threadIdx.x >> 5;
#pragma unroll
    for (int i = 0; i < 4; i++)
        t[ty + 8 * i][tx] = xb[(size_t)(c0 + ty + 8 * i) * 4096 + s0 + tx];
    __syncthreads();
#pragma unroll
    for (int i = 0; i < 4; i++)
        xtb[(size_t)(s0 + ty + 8 * i) * 512 + c0 + tx] = t[tx][ty + 8 * i];
}

// ---------------- MVN over spatial, transposed layout, 3-stage ----------------
__global__ void mvn_p1(const float* __restrict__ xt, float* __restrict__ part) {
    int ch = blockIdx.x, b = blockIdx.y;
    const float* base = xt + ((size_t)b * 4096 + ch * 256) * 512;
    int t = threadIdx.x;
    float s0 = 0, q0 = 0, s1 = 0, q1 = 0;
    for (int rr = 0; rr < 256; rr++) {
        float2 v = *(const float2*)(base + (size_t)rr * 512 + 2 * t);
        s0 += v.x; q0 += v.x * v.x;
        s1 += v.y; q1 += v.y * v.y;
    }
    *(float4*)(part + (((size_t)b * 16 + ch) * 512 + 2 * t) * 2) = make_float4(s0, q0, s1, q1);
}
__global__ void mvn_p2(const float* __restrict__ part, float2* __restrict__ minv) {
    int b = blockIdx.x, c = threadIdx.x;
    float s = 0, q = 0;
    for (int ch = 0; ch < 16; ch++) {
        float2 v = *(const float2*)(part + (((size_t)b * 16 + ch) * 512 + c) * 2);
        s += v.x; q += v.y;
    }
    float mean = s * (1.f / 4096.f);
    float var  = (q - 4096.f * mean * mean) * (1.f / 4095.f);
    minv[b * 512 + c] = make_float2(mean, rsqrtf(var + EPSV));
}
__global__ void mvn_p3(const float* __restrict__ xt, const float2* __restrict__ minv,
                       float* __restrict__ yt) {
    __shared__ float2 mi[512];
    int ch = blockIdx.x, b = blockIdx.y;
    int t = threadIdx.x;
    mi[t] = minv[b * 512 + t];
    mi[t + 256] = minv[b * 512 + t + 256];
    __syncthreads();
    const float* base = xt + ((size_t)b * 4096 + ch * 256) * 512;
    float*       ob   = yt + ((size_t)b * 4096 + ch * 256) * 512;
    float2 m0 = mi[2 * t], m1 = mi[2 * t + 1];
    for (int rr = 0; rr < 256; rr++) {
        float2 v = *(const float2*)(base + (size_t)rr * 512 + 2 * t);
        float2 o;
        o.x = (v.x - m0.x) * m0.y;
        o.y = (v.y - m1.x) * m1.y;
        *(float2*)(ob + (size_t)rr * 512 + 2 * t) = o;
    }
}

// ---------------- spatial softmax (rows of 4096, in place) ----------------
__global__ void softmax_kernel(float* __restrict__ data) {
    float* r = data + (size_t)blockIdx.x * 4096;
    int tid = threadIdx.x;
    float buf[16];
    __shared__ float sh[256];
    float m = -1e30f;
#pragma unroll
    for (int i = 0; i < 16; i++) {
        float v = r[tid + i * 256];
        buf[i] = v;
        m = fmaxf(m, v);
    }
    sh[tid] = m; __syncthreads();
    for (int o = 128; o > 0; o >>= 1) {
        if (tid < o) sh[tid] = fmaxf(sh[tid], sh[tid + o]);
        __syncthreads();
    }
    float mx = sh[0];
    __syncthreads();
    float s = 0.f;
#pragma unroll
    for (int i = 0; i < 16; i++) {
        float e = __expf(buf[i] - mx);
        buf[i] = e;
        s += e;
    }
    sh[tid] = s; __syncthreads();
    for (int o = 128; o > 0; o >>= 1) {
        if (tid < o) sh[tid] += sh[tid + o];
        __syncthreads();
    }
    float inv = 1.f / sh[0];
#pragma unroll
    for (int i = 0; i < 16; i++) r[tid + i * 256] = buf[i] * inv;
}

// ---------------- channel softmax, transposed out: T[x][y] = softmax(E[y][:])[x] ----------------
__global__ void softmaxT_kernel(const float* __restrict__ e, float* __restrict__ t) {
    int b = blockIdx.x >> 9, c = blockIdx.x & 511;
    const float* r = e + ((size_t)b * 512 + c) * 512;
    float* tb = t + (size_t)b * 512 * 512 + c;
    int tid = threadIdx.x;
    __shared__ float sh[256];
    float v0 = r[tid], v1 = r[tid + 256];
    float m = fmaxf(v0, v1);
    sh[tid] = m; __syncthreads();
    for (int o = 128; o > 0; o >>= 1) {
        if (tid < o) sh[tid] = fmaxf(sh[tid], sh[tid + o]);
        __syncthreads();
    }
    float mx = sh[0];
    __syncthreads();
    float e0 = __expf(v0 - mx), e1 = __expf(v1 - mx);
    sh[tid] = e0 + e1; __syncthreads();
    for (int o = 128; o > 0; o >>= 1) {
        if (tid < o) sh[tid] += sh[tid + o];
        __syncthreads();
    }
    float inv = 1.f / sh[0];
    tb[(size_t)tid * 512] = e0 * inv;
    tb[(size_t)(tid + 256) * 512] = e1 * inv;
}

// ---------------- tf32 mma.sync GEMM, both operands K-contiguous ----------------
// C[b][m][n] = sum_k A[b][m][k]*B[b][n][k] + bias[n] + res[b][m][n]
// transLd==0: C[row*ldc+col]; else C[col*transLd+row]. M,N%128==0, K%16==0.
#define RS  132
#define OPB (8 * RS)

__device__ __forceinline__ void mma8(float* c, const unsigned* a, const unsigned* b) {
    asm volatile(
        "mma.sync.aligned.m16n8k8.row.col.f32.tf32.tf32.f32 "
        "{%0,%1,%2,%3}, {%4,%5,%6,%7}, {%8,%9}, {%0,%1,%2,%3};"
        : "+f"(c[0]), "+f"(c[1]), "+f"(c[2]), "+f"(c[3])
        : "r"(a[0]), "r"(a[1]), "r"(a[2]), "r"(a[3]), "r"(b[0]), "r"(b[1]));
}

__global__ __launch_bounds__(256, 2) void gemm_kc(
    const float* __restrict__ A, const float* __restrict__ B, float* __restrict__ C,
    long long aBatch, int lda, long long bBatch, int ldb,
    long long cBatch, int ldc,
    const float* __restrict__ bias,
    const float* __restrict__ res, long long rBatch, int ldr,
    int K, int transLd)
{
    __shared__ float2 sm[2 * 2 * OPB];
    int tid  = threadIdx.x;
    int lane = tid & 31;
    int warp = tid >> 5;
    int bz = blockIdx.z;
    A += bz * aBatch; B += bz * bBatch; C += bz * cBatch;
    if (res) res += bz * rBatch;
    int m0 = blockIdx.y * 128, n0 = blockIdx.x * 128;
    int wm = (warp & 1) * 64, wn = (warp >> 1) * 32;

    int row = tid & 127;
    int kbf = tid >> 7;
    const float* Ap = A + (long long)(m0 + row) * lda + kbf * 8;
    const float* Bp = B + (long long)(n0 + row) * ldb + kbf * 8;

    int wIdx = kbf * 4 * RS + row;
    int r    = lane >> 2;
    int aIdx = (lane & 3) * RS + wm + r;
    int bIdx = (lane & 3) * RS + wn + r + OPB;

    float acc[4][4][4];
#pragma unroll
    for (int mt = 0; mt < 4; mt++)
#pragma unroll
        for (int nt = 0; nt < 4; nt++)
#pragma unroll
            for (int i = 0; i < 4; i++) acc[mt][nt][i] = 0.f;

    float4 a1, a2, b1, b2;
    a1 = *(const float4*)(Ap);  a2 = *(const float4*)(Ap + 4);
    b1 = *(const float4*)(Bp);  b2 = *(const float4*)(Bp + 4);
    {
        float2* w = sm + wIdx;
        w[0 * RS] = make_float2(a1.x, a2.x);
        w[1 * RS] = make_float2(a1.y, a2.y);
        w[2 * RS] = make_float2(a1.z, a2.z);
        w[3 * RS] = make_float2(a1.w, a2.w);
        float2* wB = w + OPB;
        wB[0 * RS] = make_float2(b1.x, b2.x);
        wB[1 * RS] = make_float2(b1.y, b2.y);
        wB[2 * RS] = make_float2(b1.z, b2.z);
        wB[3 * RS] = make_float2(b1.w, b2.w);
    }
    __syncthreads();

    int nch = K >> 4;
    for (int c = 0; c < nch; c++) {
        if (c + 1 < nch) {
            Ap += 16; Bp += 16;
            a1 = *(const float4*)(Ap);  a2 = *(const float4*)(Ap + 4);
            b1 = *(const float4*)(Bp);  b2 = *(const float4*)(Bp + 4);
        }
        const float2* base = sm + (c & 1) * (2 * OPB);
#pragma unroll
        for (int ks = 0; ks < 2; ks++) {
            const float2* ab = base + aIdx + ks * 4 * RS;
            const float2* bb = base + bIdx + ks * 4 * RS;
            unsigned af[4][4], bf[4][2];
#pragma unroll
            for (int mt = 0; mt < 4; mt++) {
                float2 lo = ab[mt * 16];
                float2 hi = ab[mt * 16 + 8];
                af[mt][0] = __float_as_uint(lo.x);
                af[mt][1] = __float_as_uint(hi.x);
                af[mt][2] = __float_as_uint(lo.y);
                af[mt][3] = __float_as_uint(hi.y);
            }
#pragma unroll
            for (int nt = 0; nt < 4; nt++) {
                float2 pb = bb[nt * 8];
                bf[nt][0] = __float_as_uint(pb.x);
                bf[nt][1] = __float_as_uint(pb.y);
            }
#pragma unroll
            for (int mt = 0; mt < 4; mt++)
#pragma unroll
                for (int nt = 0; nt < 4; nt++)
                    mma8(acc[mt][nt], af[mt], bf[nt]);
        }
        if (c + 1 < nch) {
            float2* w = sm + ((c + 1) & 1) * (2 * OPB) + wIdx;
            w[0 * RS] = make_float2(a1.x, a2.x);
            w[1 * RS] = make_float2(a1.y, a2.y);
            w[2 * RS] = make_float2(a1.z, a2.z);
            w[3 * RS] = make_float2(a1.w, a2.w);
            float2* wB = w + OPB;
            wB[0 * RS] = make_float2(b1.x, b2.x);
            wB[1 * RS] = make_float2(b1.y, b2.y);
            wB[2 * RS] = make_float2(b1.z, b2.z);
            wB[3 * RS] = make_float2(b1.w, b2.w);
        }
        __syncthreads();
    }

    int rwA = m0 + wm + (lane >> 2);
#pragma unroll
    for (int mt = 0; mt < 4; mt++) {
        int row0 = rwA + mt * 16;
#pragma unroll
        for (int nt = 0; nt < 4; nt++) {
            int col = n0 + wn + nt * 8 + 2 * (lane & 3);
            float bx = 0.f, by = 0.f;
            if (bias) { float2 bb = *(const float2*)(bias + col); bx = bb.x; by = bb.y; }
            float v00 = acc[mt][nt][0] + bx, v01 = acc[mt][nt][1] + by;
            float v10 = acc[mt][nt][2] + bx, v11 = acc[mt][nt][3] + by;
            if (res) {
                float2 r0 = *(const float2*)(res + (long long)row0 * ldr + col);
                float2 r1 = *(const float2*)(res + (long long)(row0 + 8) * ldr + col);
                v00 += r0.x; v01 += r0.y; v10 += r1.x; v11 += r1.y;
            }
            if (transLd == 0) {
                *(float2*)(C + (long long)row0 * ldc + col)       = make_float2(v00, v01);
                *(float2*)(C + (long long)(row0 + 8) * ldc + col) = make_float2(v10, v11);
            } else {
                C[(long long)col * transLd + row0]           = v00;
                C[(long long)(col + 1) * transLd + row0]     = v01;
                C[(long long)col * transLd + row0 + 8]       = v10;
                C[(long long)(col + 1) * transLd + row0 + 8] = v11;
            }
        }
    }
}

// ---------------- orchestration ----------------
extern "C" void kernel_launch(void* const* d_in, const int* in_sizes, int n_in,
                              void* d_out, int out_size) {
    const float* content = (const float*)d_in[0];
    const float* style   = (const float*)d_in[1];
    const float* csa_w   = (const float*)d_in[2];
    const float* csa_b   = (const float*)d_in[3];
    const float* ssa_w   = (const float*)d_in[4];
    const float* ssa_b   = (const float*)d_in[5];
    const float* ca_w    = (const float*)d_in[6];
    const float* ca_b    = (const float*)d_in[7];

    float *ct, *st, *xnt, *qkt, *v, *fg, *ht, *ot, *cft, *sft, *attn, *attnT, *part;
    float2* minv;
    cudaGetSymbolAddress((void**)&ct,    g_ct);
    cudaGetSymbolAddress((void**)&st,    g_st);
    cudaGetSymbolAddress((void**)&xnt,   g_xnt);
    cudaGetSymbolAddress((void**)&qkt,   g_qkt);
    cudaGetSymbolAddress((void**)&v,     g_v);
    cudaGetSymbolAddress((void**)&fg,    g_fg);
    cudaGetSymbolAddress((void**)&ht,    g_ht);
    cudaGetSymbolAddress((void**)&ot,    g_ot);
    cudaGetSymbolAddress((void**)&cft,   g_cft);
    cudaGetSymbolAddress((void**)&sft,   g_sft);
    cudaGetSymbolAddress((void**)&attn,  g_attn);
    cudaGetSymbolAddress((void**)&attnT, g_attnT);
    cudaGetSymbolAddress((void**)&part,  g_part);
    cudaGetSymbolAddress((void**)&minv,  g_minv);

    const int B = 4;
    dim3 trGrid(128, 16, B);
    dim3 mvnGrid(16, B);
    dim3 convG(4, 32, B);
    dim3 qkG(8, 32, B);
    dim3 enG(32, 32, B);
    dim3 chG(4, 4, B);

    auto MVN = [&](const float* x, float* y) {
        mvn_p1<<<mvnGrid, 256>>>(x, part);
        mvn_p2<<<B, 512>>>(part, minv);
        mvn_p3<<<mvnGrid, 256>>>(x, minv, y);
    };

    transp_kernel<<<trGrid, 256>>>(content, ct);
    transp_kernel<<<trGrid, 256>>>(style, st);

    // ================= content self-attention =================
    MVN(ct, xnt);
    gemm_kc<<<qkG, 256>>>(xnt, csa_w, qkt, CNE, 512, 0, 512, QKB, 1024,
                          csa_b, nullptr, 0, 0, 512, 0);
    gemm_kc<<<convG, 256>>>(ct, csa_w + 2 * WWE, v, CNE, 512, 0, 512, CNE, 0,
                            csa_b + 2 * 512, nullptr, 0, 0, 512, 4096);
    gemm_kc<<<enG, 256>>>(qkt, qkt + 512, attn, QKB, 1024, QKB, 1024, NNE, 4096,
                          nullptr, nullptr, 0, 0, 512, 0);
    softmax_kernel<<<B * 4096, 256>>>(attn);
    gemm_kc<<<convG, 256>>>(attn, v, ot, NNE, 4096, CNE, 4096, CNE, 512,
                            nullptr, nullptr, 0, 0, 4096, 0);
    gemm_kc<<<convG, 256>>>(ot, csa_w + 3 * WWE, cft, CNE, 512, 0, 512, CNE, 512,
                            csa_b + 3 * 512, ct, CNE, 512, 512, 0);

    // ================= style self-attention (channel attention) =================
    MVN(st, xnt);
    gemm_kc<<<qkG, 256>>>(st, ssa_w, fg, CNE, 512, 0, 512, QKB, 0,
                          ssa_b, nullptr, 0, 0, 512, 4096);
    gemm_kc<<<convG, 256>>>(xnt, ssa_w + 2 * WWE, ht, CNE, 512, 0, 512, CNE, 512,
                            ssa_b + 2 * 512, nullptr, 0, 0, 512, 0);
    gemm_kc<<<chG, 256>>>(fg, fg + (long long)512 * 4096, attn, QKB, 4096, QKB, 4096,
                          CCB, 512, nullptr, nullptr, 0, 0, 4096, 0);
    softmaxT_kernel<<<B * 512, 256>>>(attn, attnT);
    gemm_kc<<<convG, 256>>>(ht, attnT, ot, CNE, 512, CCB, 512, CNE, 512,
                            nullptr, nullptr, 0, 0, 512, 0);
    gemm_kc<<<convG, 256>>>(ot, ssa_w + 3 * WWE, sft, CNE, 512, 0, 512, CNE, 512,
                            ssa_b + 3 * 512, st, CNE, 512, 512, 0);

    // ================= cross attention =================
    MVN(cft, xnt);
    gemm_kc<<<convG, 256>>>(xnt, ca_w, qkt, CNE, 512, 0, 512, QKB, 1024,
                            ca_b, nullptr, 0, 0, 512, 0);
    MVN(sft, xnt);
    gemm_kc<<<convG, 256>>>(xnt, ca_w + WWE, qkt + 512, CNE, 512, 0, 512, QKB, 1024,
                            ca_b + 512, nullptr, 0, 0, 512, 0);
    gemm_kc<<<convG, 256>>>(sft, ca_w + 2 * WWE, v, CNE, 512, 0, 512, CNE, 0,
                            ca_b + 2 * 512, nullptr, 0, 0, 512, 4096);
    gemm_kc<<<enG, 256>>>(qkt, qkt + 512, attn, QKB, 1024, QKB, 1024, NNE, 4096,
                          nullptr, nullptr, 0, 0, 512, 0);
    softmax_kernel<<<B * 4096, 256>>>(attn);
    gemm_kc<<<convG, 256>>>(attn, v, ot, NNE, 4096, CNE, 4096, CNE, 512,
                            nullptr, nullptr, 0, 0, 4096, 0);
    gemm_kc<<<convG, 256>>>(ot, ca_w + 3 * WWE, (float*)d_out, CNE, 512, 0, 512, CNE, 0,
                            ca_b + 3 * 512, cft, CNE, 512, 512, 4096);
}

// round 7
// speedup vs baseline: 1.1091x; 1.1091x over previous
#include <cuda_runtime.h>
#include <cstdint>
#include <math.h>

#define EPSV 1e-5f

static const int BATCH = 4;
static const int CCH   = 512;
static const int NSP   = 4096;   // H*W

// ---------------- scratch (device globals; no runtime allocation) ----------------
__device__ float g_xn [(size_t)4 * 512 * 4096];
__device__ float g_q  [(size_t)4 * 512 * 4096];
__device__ float g_k  [(size_t)4 * 512 * 4096];
__device__ float g_v  [(size_t)4 * 512 * 4096];
__device__ float g_o  [(size_t)4 * 512 * 4096];
__device__ float g_cf [(size_t)4 * 512 * 4096];
__device__ float g_sf [(size_t)4 * 512 * 4096];
__device__ float g_attn[(size_t)4 * 4096 * 4096];

// ---------------- helpers ----------------
__device__ __forceinline__ unsigned f2tf(float x) {
    unsigned u;
    asm("cvt.rna.tf32.f32 %0, %1;" : "=r"(u) : "f"(x));
    return u;
}
__device__ __forceinline__ float rndtf(float x) {
    return __uint_as_float(f2tf(x));
}

__device__ __forceinline__ void mma8(float* c, const unsigned* a, const unsigned* b) {
    asm volatile(
        "mma.sync.aligned.m16n8k8.row.col.f32.tf32.tf32.f32 "
        "{%0,%1,%2,%3}, {%4,%5,%6,%7}, {%8,%9}, {%0,%1,%2,%3};"
        : "+f"(c[0]), "+f"(c[1]), "+f"(c[2]), "+f"(c[3])
        : "r"(a[0]), "r"(a[1]), "r"(a[2]), "r"(a[3]), "r"(b[0]), "r"(b[1]));
}

// ---------------- MVN (unbiased var, ddof=1), output tf32-rounded ----------------
__global__ void mvn_kernel(const float* __restrict__ x, float* __restrict__ y, int n) {
    const float* xr = x + (size_t)blockIdx.x * n;
    float*       yr = y + (size_t)blockIdx.x * n;
    int tid = threadIdx.x;
    float s = 0.f, s2 = 0.f;
    for (int i = tid; i < n; i += blockDim.x) {
        float v = xr[i];
        s += v; s2 += v * v;
    }
    __shared__ float sh0[256];
    __shared__ float sh1[256];
    sh0[tid] = s; sh1[tid] = s2;
    __syncthreads();
    for (int o = 128; o > 0; o >>= 1) {
        if (tid < o) { sh0[tid] += sh0[tid + o]; sh1[tid] += sh1[tid + o]; }
        __syncthreads();
    }
    float mean = sh0[0] / (float)n;
    float var  = (sh1[0] - (float)n * mean * mean) / (float)(n - 1);
    float inv  = rsqrtf(var + EPSV);
    for (int i = tid; i < n; i += blockDim.x) {
        yr[i] = rndtf((xr[i] - mean) * inv);
    }
}

// ---------------- row softmax (in place), output tf32-rounded ----------------
__global__ void softmax_kernel(float* __restrict__ data, int n) {
    float* r = data + (size_t)blockIdx.x * n;
    int tid = threadIdx.x;
    int per = n / blockDim.x;       // 16 (spatial) or 2 (channel)
    float buf[16];
    __shared__ float sh[256];

    float m = -1e30f;
#pragma unroll 16
    for (int i = 0; i < 16; i++) {
        if (i < per) {
            float v = r[tid + i * blockDim.x];
            buf[i] = v;
            m = fmaxf(m, v);
        }
    }
    sh[tid] = m; __syncthreads();
    for (int o = 128; o > 0; o >>= 1) {
        if (tid < o) sh[tid] = fmaxf(sh[tid], sh[tid + o]);
        __syncthreads();
    }
    float mx = sh[0];
    __syncthreads();

    float s = 0.f;
#pragma unroll 16
    for (int i = 0; i < 16; i++) {
        if (i < per) {
            float e = __expf(buf[i] - mx);
            buf[i] = e;
            s += e;
        }
    }
    sh[tid] = s; __syncthreads();
    for (int o = 128; o > 0; o >>= 1) {
        if (tid < o) sh[tid] += sh[tid + o];
        __syncthreads();
    }
    float inv = 1.f / sh[0];
#pragma unroll 16
    for (int i = 0; i < 16; i++) {
        if (i < per) r[tid + i * blockDim.x] = rndtf(buf[i] * inv);
    }
}

// ---------------- TF32 tensor-core batched GEMM, generic strides ----------------
// C[b][m][n] = sum_k A(m,k)*B(k,n) + bias[m] + res[b][m][n]
// A(m,k) = A[b*aBatch + m*sam + k*sak]  (either sak==1 or sam==1)
// B(k,n) = B[b*bBatch + k*sbk + n*sbn]  (either sbk==1 or sbn==1)
// cvA/cvB: apply cvt.rna.tf32 during staging (for raw-f32 operands).
// rnd: round outputs to tf32 in epilogue (for outputs that feed other GEMMs).
// Requires M%128==0, N%128==0, K%16==0.
#define RS 132   // row stride in float2 units (128 + 4 pad)
__global__ __launch_bounds__(256) void gemm_tc(
    const float* __restrict__ A, const float* __restrict__ Bp, float* __restrict__ C,
    long long aBatch, long long sam, long long sak,
    long long bBatch, long long sbk, long long sbn,
    long long cBatch,
    const float* __restrict__ bias,
    const float* __restrict__ res, long long rBatch,
    int M, int N, int K, int cvA, int cvB, int rnd)
{
    const int BM = 128, BK = 16;
    __shared__ float2 As2[8][RS];
    __shared__ float2 Bs2[8][RS];

    int bz = blockIdx.z;
    A  += (long long)bz * aBatch;
    Bp += (long long)bz * bBatch;
    C  += (long long)bz * cBatch;
    if (res) res += (long long)bz * rBatch;

    int tid  = threadIdx.x;
    int lane = tid & 31;
    int warp = tid >> 5;
    int m0 = blockIdx.y * BM;
    int n0 = blockIdx.x * BM;
    int wm = (warp & 1) * 64;   // 2 warps along M
    int wn = (warp >> 1) * 32;  // 4 warps along N

    bool aK = (sak == 1);
    bool bK = (sbk == 1);

    // ---- loader descriptors ----
    int a_row = 0, a_sel = 0, a_m4 = 0, a_kk = 0;
    long long aOff, aStep, aD2;
    if (aK) {
        a_row = tid >> 1; a_sel = (tid & 1) * 4;
        aOff = (long long)(m0 + a_row) * sam + (tid & 1) * 8;
        aStep = 16; aD2 = 4;
    } else {  // sam == 1
        a_m4 = (tid & 31) * 4; a_kk = tid >> 5;
        aOff = (long long)(m0 + a_m4) + (long long)a_kk * sak;
        aStep = 16 * sak; aD2 = 8 * sak;
    }
    int b_row = 0, b_sel = 0, b_n4 = 0, b_kk = 0;
    long long bOff, bStep, bD2;
    if (bK) {
        b_row = tid >> 1; b_sel = (tid & 1) * 4;
        bOff = (long long)(n0 + b_row) * sbn + (tid & 1) * 8;
        bStep = 16; bD2 = 4;
    } else {  // sbn == 1
        b_n4 = (tid & 31) * 4; b_kk = tid >> 5;
        bOff = (long long)(n0 + b_n4) + (long long)b_kk * sbk;
        bStep = 16 * sbk; bD2 = 8 * sbk;
    }

    // fragment read indices (float2 units) — identical to r3
    int r = lane >> 2;
    const unsigned aIdx = (unsigned)((lane & 3) * RS + wm + r);
    const unsigned bIdx = (unsigned)((lane & 3) * RS + wn + r);
    const float2* a2p = &As2[0][0];
    const float2* b2p = &Bs2[0][0];

    float acc[4][4][4];
#pragma unroll
    for (int mt = 0; mt < 4; mt++)
#pragma unroll
        for (int nt = 0; nt < 4; nt++)
#pragma unroll
            for (int i = 0; i < 4; i++) acc[mt][nt][i] = 0.f;

    float4 pa0, pa1, pb0, pb1;
    pa0 = *(const float4*)(A + aOff);
    pa1 = *(const float4*)(A + aOff + aD2);
    pb0 = *(const float4*)(Bp + bOff);
    pb1 = *(const float4*)(Bp + bOff + bD2);

    for (int k0 = 0; k0 < K; k0 += BK) {
        // ---- stage A ----
        {
            float x0[4] = {pa0.x, pa0.y, pa0.z, pa0.w};
            float x1[4] = {pa1.x, pa1.y, pa1.z, pa1.w};
            if (aK) {
                float2* w = &As2[a_sel][a_row];
                if (cvA) {
#pragma unroll
                    for (int j = 0; j < 4; j++)
                        w[j * RS] = make_float2(__uint_as_float(f2tf(x0[j])),
                                                __uint_as_float(f2tf(x1[j])));
                } else {
#pragma unroll
                    for (int j = 0; j < 4; j++)
                        w[j * RS] = make_float2(x0[j], x1[j]);
                }
            } else {
#pragma unroll
                for (int j = 0; j < 2; j++) {
                    int k = a_kk + 8 * j;
                    int p = ((k >> 3) << 2) | (k & 3);
                    int h = (k >> 2) & 1;
                    const float* src = j ? x1 : x0;
#pragma unroll
                    for (int i = 0; i < 4; i++) {
                        unsigned bits = cvA ? f2tf(src[i]) : __float_as_uint(src[i]);
                        ((unsigned*)&As2[p][a_m4 + i])[h] = bits;
                    }
                }
            }
        }
        // ---- stage B ----
        {
            float x0[4] = {pb0.x, pb0.y, pb0.z, pb0.w};
            float x1[4] = {pb1.x, pb1.y, pb1.z, pb1.w};
            if (bK) {
                float2* w = &Bs2[b_sel][b_row];
                if (cvB) {
#pragma unroll
                    for (int j = 0; j < 4; j++)
                        w[j * RS] = make_float2(__uint_as_float(f2tf(x0[j])),
                                                __uint_as_float(f2tf(x1[j])));
                } else {
#pragma unroll
                    for (int j = 0; j < 4; j++)
                        w[j * RS] = make_float2(x0[j], x1[j]);
                }
            } else {
#pragma unroll
                for (int j = 0; j < 2; j++) {
                    int k = b_kk + 8 * j;
                    int p = ((k >> 3) << 2) | (k & 3);
                    int h = (k >> 2) & 1;
                    const float* src = j ? x1 : x0;
#pragma unroll
                    for (int i = 0; i < 4; i++) {
                        unsigned bits = cvB ? f2tf(src[i]) : __float_as_uint(src[i]);
                        ((unsigned*)&Bs2[p][b_n4 + i])[h] = bits;
                    }
                }
            }
        }
        __syncthreads();

        // prefetch next tile
        aOff += aStep;
        bOff += bStep;
        if (k0 + BK < K) {
            pa0 = *(const float4*)(A + aOff);
            pa1 = *(const float4*)(A + aOff + aD2);
            pb0 = *(const float4*)(Bp + bOff);
            pb1 = *(const float4*)(Bp + bOff + bD2);
        }

        // compute 2 k-slices of 8
#pragma unroll
        for (int ks = 0; ks < 2; ks++) {
            const unsigned off = ks * (4u * RS);
            unsigned af[4][4], bf[4][2];
#pragma unroll
            for (int mt = 0; mt < 4; mt++) {
                float2 lo = a2p[aIdx + off + mt * 16];
                float2 hi = a2p[aIdx + off + mt * 16 + 8];
                af[mt][0] = __float_as_uint(lo.x);
                af[mt][1] = __float_as_uint(hi.x);
                af[mt][2] = __float_as_uint(lo.y);
                af[mt][3] = __float_as_uint(hi.y);
            }
#pragma unroll
            for (int nt = 0; nt < 4; nt++) {
                float2 pb = b2p[bIdx + off + nt * 8];
                bf[nt][0] = __float_as_uint(pb.x);
                bf[nt][1] = __float_as_uint(pb.y);
            }
#pragma unroll
            for (int mt = 0; mt < 4; mt++)
#pragma unroll
                for (int nt = 0; nt < 4; nt++)
                    mma8(acc[mt][nt], af[mt], bf[nt]);
        }
        __syncthreads();
    }

    // epilogue: bias (per-row) + residual, optional tf32 rounding, float2 stores
#pragma unroll
    for (int mt = 0; mt < 4; mt++) {
        int row = m0 + wm + mt * 16 + (lane >> 2);
        float bi0 = bias ? bias[row]     : 0.f;
        float bi1 = bias ? bias[row + 8] : 0.f;
#pragma unroll
        for (int nt = 0; nt < 4; nt++) {
            int col = n0 + wn + nt * 8 + 2 * (lane & 3);
            float v00 = acc[mt][nt][0] + bi0, v01 = acc[mt][nt][1] + bi0;
            float v10 = acc[mt][nt][2] + bi1, v11 = acc[mt][nt][3] + bi1;
            if (res) {
                float2 r0 = *(const float2*)(res + (long long)row * N + col);
                float2 r1 = *(const float2*)(res + (long long)(row + 8) * N + col);
                v00 += r0.x; v01 += r0.y; v10 += r1.x; v11 += r1.y;
            }
            if (rnd) {
                v00 = rndtf(v00); v01 = rndtf(v01);
                v10 = rndtf(v10); v11 = rndtf(v11);
            }
            *(float2*)(C + (long long)row * N + col)       = make_float2(v00, v01);
            *(float2*)(C + (long long)(row + 8) * N + col) = make_float2(v10, v11);
        }
    }
}

// ---------------- orchestration ----------------
extern "C" void kernel_launch(void* const* d_in, const int* in_sizes, int n_in,
                              void* d_out, int out_size) {
    const float* content = (const float*)d_in[0];
    const float* style   = (const float*)d_in[1];
    const float* csa_w   = (const float*)d_in[2];
    const float* csa_b   = (const float*)d_in[3];
    const float* ssa_w   = (const float*)d_in[4];
    const float* ssa_b   = (const float*)d_in[5];
    const float* ca_w    = (const float*)d_in[6];
    const float* ca_b    = (const float*)d_in[7];

    float *xn, *q, *k, *v, *o, *cf, *sf, *attn;
    cudaGetSymbolAddress((void**)&xn,   g_xn);
    cudaGetSymbolAddress((void**)&q,    g_q);
    cudaGetSymbolAddress((void**)&k,    g_k);
    cudaGetSymbolAddress((void**)&v,    g_v);
    cudaGetSymbolAddress((void**)&o,    g_o);
    cudaGetSymbolAddress((void**)&cf,   g_cf);
    cudaGetSymbolAddress((void**)&sf,   g_sf);
    cudaGetSymbolAddress((void**)&attn, g_attn);

    const int B = BATCH, C = CCH, N = NSP;
    const long long CN = (long long)C * N;
    const long long NN = (long long)N * N;
    const long long WW = (long long)C * C;

    dim3 convGrid(N / 128, C / 128, B);   // (32,4,4)
    dim3 enGrid  (N / 128, N / 128, B);   // (32,32,4)
    dim3 chGrid  (C / 128, C / 128, B);   // (4,4,4)

    // ================= content self-attention =================
    mvn_kernel<<<B * C, 256>>>(content, xn, N);
    gemm_tc<<<convGrid, 256>>>(csa_w + 0 * WW, xn,      q, 0, C, 1, CN, N, 1, CN, csa_b + 0 * C, nullptr, 0, C, N, C, 1, 0, 1);
    gemm_tc<<<convGrid, 256>>>(csa_w + 1 * WW, xn,      k, 0, C, 1, CN, N, 1, CN, csa_b + 1 * C, nullptr, 0, C, N, C, 1, 0, 1);
    gemm_tc<<<convGrid, 256>>>(csa_w + 2 * WW, content, v, 0, C, 1, CN, N, 1, CN, csa_b + 2 * C, nullptr, 0, C, N, C, 1, 1, 1);
    // E[i,j] = sum_c q[c,i] k[c,j]
    gemm_tc<<<enGrid, 256>>>(q, k, attn, CN, 1, N, CN, N, 1, NN, nullptr, nullptr, 0, N, N, C, 0, 0, 0);
    softmax_kernel<<<B * N, 256>>>(attn, N);
    // O[c,i] = sum_j v[c,j] attn[i,j]
    gemm_tc<<<convGrid, 256>>>(v, attn, o, CN, N, 1, NN, 1, N, CN, nullptr, nullptr, 0, C, N, N, 0, 0, 1);
    gemm_tc<<<convGrid, 256>>>(csa_w + 3 * WW, o, cf, 0, C, 1, CN, N, 1, CN, csa_b + 3 * C, content, CN, C, N, C, 1, 0, 0);

    // ================= style self-attention (channel attention) =================
    mvn_kernel<<<B * C, 256>>>(style, xn, N);
    gemm_tc<<<convGrid, 256>>>(ssa_w + 0 * WW, style, q, 0, C, 1, CN, N, 1, CN, ssa_b + 0 * C, nullptr, 0, C, N, C, 1, 1, 1); // f
    gemm_tc<<<convGrid, 256>>>(ssa_w + 1 * WW, style, k, 0, C, 1, CN, N, 1, CN, ssa_b + 1 * C, nullptr, 0, C, N, C, 1, 1, 1); // g
    gemm_tc<<<convGrid, 256>>>(ssa_w + 2 * WW, xn,    v, 0, C, 1, CN, N, 1, CN, ssa_b + 2 * C, nullptr, 0, C, N, C, 1, 0, 1); // h
    // E[c,d] = sum_i f[c,i] g[d,i]
    gemm_tc<<<chGrid, 256>>>(q, k, attn, CN, N, 1, CN, 1, N, WW, nullptr, nullptr, 0, C, C, N, 0, 0, 0);
    softmax_kernel<<<B * C, 256>>>(attn, C);
    // O[c,i] = sum_d attn[d,c] h[d,i]
    gemm_tc<<<convGrid, 256>>>(attn, v, o, WW, 1, C, CN, N, 1, CN, nullptr, nullptr, 0, C, N, C, 0, 0, 1);
    gemm_tc<<<convGrid, 256>>>(ssa_w + 3 * WW, o, sf, 0, C, 1, CN, N, 1, CN, ssa_b + 3 * C, style, CN, C, N, C, 1, 0, 0);

    // ================= cross attention =================
    mvn_kernel<<<B * C, 256>>>(cf, xn, N);
    gemm_tc<<<convGrid, 256>>>(ca_w + 0 * WW, xn, q, 0, C, 1, CN, N, 1, CN, ca_b + 0 * C, nullptr, 0, C, N, C, 1, 0, 1);
    mvn_kernel<<<B * C, 256>>>(sf, xn, N);
    gemm_tc<<<convGrid, 256>>>(ca_w + 1 * WW, xn, k, 0, C, 1, CN, N, 1, CN, ca_b + 1 * C, nullptr, 0, C, N, C, 1, 0, 1);
    gemm_tc<<<convGrid, 256>>>(ca_w + 2 * WW, sf, v, 0, C, 1, CN, N, 1, CN, ca_b + 2 * C, nullptr, 0, C, N, C, 1, 1, 1);
    gemm_tc<<<enGrid, 256>>>(q, k, attn, CN, 1, N, CN, N, 1, NN, nullptr, nullptr, 0, N, N, C, 0, 0, 0);
    softmax_kernel<<<B * N, 256>>>(attn, N);
    gemm_tc<<<convGrid, 256>>>(v, attn, o, CN, N, 1, NN, 1, N, CN, nullptr, nullptr, 0, C, N, N, 0, 0, 1);
    gemm_tc<<<convGrid, 256>>>(ca_w + 3 * WW, o, (float*)d_out, 0, C, 1, CN, N, 1, CN, ca_b + 3 * C, cf, CN, C, N, C, 1, 0, 0);
}

// round 8
// speedup vs baseline: 1.1303x; 1.0191x over previous
#include <cuda_runtime.h>
#include <math.h>

#define EPSV 1e-5f

static const int BATCH = 4;
static const int CCH   = 512;
static const int NSP   = 4096;   // H*W

// ---------------- scratch (device globals; no runtime allocation) ----------------
__device__ float g_xn [(size_t)4 * 512 * 4096];
__device__ float g_q  [(size_t)4 * 512 * 4096];
__device__ float g_k  [(size_t)4 * 512 * 4096];
__device__ float g_v  [(size_t)4 * 512 * 4096];
__device__ float g_o  [(size_t)4 * 512 * 4096];
__device__ float g_cf [(size_t)4 * 512 * 4096];
__device__ float g_sf [(size_t)4 * 512 * 4096];
__device__ float g_attn[(size_t)4 * 4096 * 4096];

// ---------------- helpers ----------------
__device__ __forceinline__ unsigned f2tf(float x) {
    unsigned u;
    asm("cvt.rna.tf32.f32 %0, %1;" : "=r"(u) : "f"(x));
    return u;
}

__device__ __forceinline__ void mma8(float* c, const unsigned* a, const unsigned* b) {
    asm volatile(
        "mma.sync.aligned.m16n8k8.row.col.f32.tf32.tf32.f32 "
        "{%0,%1,%2,%3}, {%4,%5,%6,%7}, {%8,%9}, {%0,%1,%2,%3};"
        : "+f"(c[0]), "+f"(c[1]), "+f"(c[2]), "+f"(c[3])
        : "r"(a[0]), "r"(a[1]), "r"(a[2]), "r"(a[3]), "r"(b[0]), "r"(b[1]));
}

// ---------------- MVN: per-row mean/var normalize (unbiased var, ddof=1) ----------------
__global__ void mvn_kernel(const float* __restrict__ x, float* __restrict__ y, int n) {
    const float* xr = x + (size_t)blockIdx.x * n;
    float*       yr = y + (size_t)blockIdx.x * n;
    int tid = threadIdx.x;
    float s = 0.f, s2 = 0.f;
    for (int i = tid; i < n; i += blockDim.x) {
        float v = xr[i];
        s += v; s2 += v * v;
    }
    __shared__ float sh0[256];
    __shared__ float sh1[256];
    sh0[tid] = s; sh1[tid] = s2;
    __syncthreads();
    for (int o = 128; o > 0; o >>= 1) {
        if (tid < o) { sh0[tid] += sh0[tid + o]; sh1[tid] += sh1[tid + o]; }
        __syncthreads();
    }
    float mean = sh0[0] / (float)n;
    float var  = (sh1[0] - (float)n * mean * mean) / (float)(n - 1);
    float inv  = rsqrtf(var + EPSV);
    for (int i = tid; i < n; i += blockDim.x) {
        yr[i] = (xr[i] - mean) * inv;
    }
}

// ---------------- row softmax (in place), row cached in registers ----------------
__global__ void softmax_kernel(float* __restrict__ data, int n) {
    float* r = data + (size_t)blockIdx.x * n;
    int tid = threadIdx.x;
    int per = n / blockDim.x;       // 16 (spatial) or 2 (channel)
    float buf[16];
    __shared__ float sh[256];

    float m = -1e30f;
#pragma unroll 16
    for (int i = 0; i < 16; i++) {
        if (i < per) {
            float v = r[tid + i * blockDim.x];
            buf[i] = v;
            m = fmaxf(m, v);
        }
    }
    sh[tid] = m; __syncthreads();
    for (int o = 128; o > 0; o >>= 1) {
        if (tid < o) sh[tid] = fmaxf(sh[tid], sh[tid + o]);
        __syncthreads();
    }
    float mx = sh[0];
    __syncthreads();

    float s = 0.f;
#pragma unroll 16
    for (int i = 0; i < 16; i++) {
        if (i < per) {
            float e = __expf(buf[i] - mx);
            buf[i] = e;
            s += e;
        }
    }
    sh[tid] = s; __syncthreads();
    for (int o = 128; o > 0; o >>= 1) {
        if (tid < o) sh[tid] += sh[tid + o];
        __syncthreads();
    }
    float inv = 1.f / sh[0];
#pragma unroll 16
    for (int i = 0; i < 16; i++) {
        if (i < per) r[tid + i * blockDim.x] = buf[i] * inv;
    }
}

// ---------------- TF32 tensor-core batched GEMM, generic strides ----------------
// Identical to the proven r3 kernel EXCEPT: double-buffered smem with a single
// __syncthreads per k-tile (barrier sits between stage and compute).
// Paired-k smem layout: As2[p][m] = float2( elem(k), elem(k+4) ),
//   p = ((k>>3)<<2) | (k&3),  component = (k>>2)&1.
// Requires M%128==0, N%128==0, K%16==0.
#define RS 132          // row stride in float2 units (128 + 4 pad)
#define BUF (8 * RS)    // one operand buffer, float2 units
__global__ __launch_bounds__(256) void gemm_tc(
    const float* __restrict__ A, const float* __restrict__ Bp, float* __restrict__ C,
    long long aBatch, long long sam, long long sak,
    long long bBatch, long long sbk, long long sbn,
    long long cBatch,
    const float* __restrict__ bias,
    const float* __restrict__ res, long long rBatch,
    int M, int N, int K)
{
    const int BM = 128, BK = 16;
    __shared__ float2 As2[2][8][RS];
    __shared__ float2 Bs2[2][8][RS];

    int bz = blockIdx.z;
    A  += (long long)bz * aBatch;
    Bp += (long long)bz * bBatch;
    C  += (long long)bz * cBatch;
    if (res) res += (long long)bz * rBatch;

    int tid  = threadIdx.x;
    int lane = tid & 31;
    int warp = tid >> 5;
    int m0 = blockIdx.y * BM;
    int n0 = blockIdx.x * BM;
    int wm = (warp & 1) * 64;   // 2 warps along M
    int wn = (warp >> 1) * 32;  // 4 warps along N

    bool aK = (sak == 1);
    bool bK = (sbk == 1);

    // per-thread global-load descriptors (8 elems per operand per tile) — r3 pattern
    int a_kk, a_mm; long long aOff, aStep;
    if (aK) { a_kk = tid & 15; a_mm = tid >> 4;
              aOff = (long long)(m0 + a_mm) * sam + a_kk; aStep = 16 * sam; }
    else    { a_mm = tid & 127; a_kk = tid >> 7;
              aOff = (long long)(m0 + a_mm) * sam + (long long)a_kk * sak; aStep = 2 * sak; }
    int b_kk, b_nn; long long bOff, bStep;
    if (bK) { b_kk = tid & 15; b_nn = tid >> 4;
              bOff = (long long)(n0 + b_nn) * sbn + b_kk; bStep = 16 * sbn; }
    else    { b_nn = tid & 127; b_kk = tid >> 7;
              bOff = (long long)(n0 + b_nn) * sbn + (long long)b_kk * sbk; bStep = 2 * sbk; }

    // precomputed smem write targets
    int ap = ((a_kk >> 3) << 2) | (a_kk & 3);
    int ah = (a_kk >> 2) & 1;
    int bp = ((b_kk >> 3) << 2) | (b_kk & 3);
    int bh = (b_kk >> 2) & 1;

    // precomputed fragment read indices (float2 units)
    int r = lane >> 2;
    const unsigned aIdx = (unsigned)((lane & 3) * RS + wm + r);
    const unsigned bIdx = (unsigned)((lane & 3) * RS + wn + r);
    const float2* a2p = &As2[0][0][0];
    const float2* b2p = &Bs2[0][0][0];

    float acc[4][4][4];
#pragma unroll
    for (int mt = 0; mt < 4; mt++)
#pragma unroll
        for (int nt = 0; nt < 4; nt++)
#pragma unroll
            for (int i = 0; i < 4; i++) acc[mt][nt][i] = 0.f;

    float ra[8], rb[8];
#pragma unroll
    for (int i = 0; i < 8; i++) ra[i] = A[aOff + i * aStep];
#pragma unroll
    for (int i = 0; i < 8; i++) rb[i] = Bp[bOff + i * bStep];

    int nch = K / BK;
    for (int c = 0; c < nch; c++) {
        unsigned bsel = (unsigned)(c & 1) * BUF;

        // ---- stage tile c (registers -> smem buffer c&1, tf32 converted) ----
        if (aK) {
            unsigned* dst = (unsigned*)&As2[c & 1][ap][a_mm] + ah;
#pragma unroll
            for (int i = 0; i < 8; i++) dst[32 * i] = f2tf(ra[i]);
        } else {
#pragma unroll
            for (int i = 0; i < 8; i++) {
                int k = a_kk + 2 * i;
                int p = ((k >> 3) << 2) | (k & 3);
                int h = (k >> 2) & 1;
                ((unsigned*)&As2[c & 1][p][a_mm])[h] = f2tf(ra[i]);
            }
        }
        if (bK) {
            unsigned* dst = (unsigned*)&Bs2[c & 1][bp][b_nn] + bh;
#pragma unroll
            for (int i = 0; i < 8; i++) dst[32 * i] = f2tf(rb[i]);
        } else {
#pragma unroll
            for (int i = 0; i < 8; i++) {
                int k = b_kk + 2 * i;
                int p = ((k >> 3) << 2) | (k & 3);
                int h = (k >> 2) & 1;
                ((unsigned*)&Bs2[c & 1][p][b_nn])[h] = f2tf(rb[i]);
            }
        }

        // ---- prefetch tile c+1 globals into registers (in flight during compute) ----
        aOff += (long long)BK * sak;
        bOff += (long long)BK * sbk;
        if (c + 1 < nch) {
#pragma unroll
            for (int i = 0; i < 8; i++) ra[i] = A[aOff + i * aStep];
#pragma unroll
            for (int i = 0; i < 8; i++) rb[i] = Bp[bOff + i * bStep];
        }

        // single barrier per tile: stage(c) visible to all before compute(c);
        // also orders this warp's upcoming stage(c+1) after all warps' compute(c-1).
        __syncthreads();

        // ---- compute 2 k-slices of 8 from buffer c&1 ----
#pragma unroll
        for (int ks = 0; ks < 2; ks++) {
            const unsigned off = bsel + ks * (4u * RS);
            unsigned af[4][4], bf[4][2];
#pragma unroll
            for (int mt = 0; mt < 4; mt++) {
                float2 lo = a2p[aIdx + off + mt * 16];
                float2 hi = a2p[aIdx + off + mt * 16 + 8];
                af[mt][0] = __float_as_uint(lo.x);
                af[mt][1] = __float_as_uint(hi.x);
                af[mt][2] = __float_as_uint(lo.y);
                af[mt][3] = __float_as_uint(hi.y);
            }
#pragma unroll
            for (int nt = 0; nt < 4; nt++) {
                float2 pb = b2p[bIdx + off + nt * 8];
                bf[nt][0] = __float_as_uint(pb.x);
                bf[nt][1] = __float_as_uint(pb.y);
            }
#pragma unroll
            for (int mt = 0; mt < 4; mt++)
#pragma unroll
                for (int nt = 0; nt < 4; nt++)
                    mma8(acc[mt][nt], af[mt], bf[nt]);
        }
    }

    // epilogue: bias + residual, float2 stores
#pragma unroll
    for (int mt = 0; mt < 4; mt++) {
        int row = m0 + wm + mt * 16 + (lane >> 2);
        float bi0 = bias ? bias[row]     : 0.f;
        float bi1 = bias ? bias[row + 8] : 0.f;
#pragma unroll
        for (int nt = 0; nt < 4; nt++) {
            int col = n0 + wn + nt * 8 + 2 * (lane & 3);
            float2 v0 = make_float2(acc[mt][nt][0] + bi0, acc[mt][nt][1] + bi0);
            float2 v1 = make_float2(acc[mt][nt][2] + bi1, acc[mt][nt][3] + bi1);
            if (res) {
                float2 r0 = *(const float2*)(res + (long long)row * N + col);
                float2 r1 = *(const float2*)(res + (long long)(row + 8) * N + col);
                v0.x += r0.x; v0.y += r0.y;
                v1.x += r1.x; v1.y += r1.y;
            }
            *(float2*)(C + (long long)row * N + col)       = v0;
            *(float2*)(C + (long long)(row + 8) * N + col) = v1;
        }
    }
}

// ---------------- orchestration ----------------
extern "C" void kernel_launch(void* const* d_in, const int* in_sizes, int n_in,
                              void* d_out, int out_size) {
    const float* content = (const float*)d_in[0];
    const float* style   = (const float*)d_in[1];
    const float* csa_w   = (const float*)d_in[2];
    const float* csa_b   = (const float*)d_in[3];
    const float* ssa_w   = (const float*)d_in[4];
    const float* ssa_b   = (const float*)d_in[5];
    const float* ca_w    = (const float*)d_in[6];
    const float* ca_b    = (const float*)d_in[7];

    float *xn, *q, *k, *v, *o, *cf, *sf, *attn;
    cudaGetSymbolAddress((void**)&xn,   g_xn);
    cudaGetSymbolAddress((void**)&q,    g_q);
    cudaGetSymbolAddress((void**)&k,    g_k);
    cudaGetSymbolAddress((void**)&v,    g_v);
    cudaGetSymbolAddress((void**)&o,    g_o);
    cudaGetSymbolAddress((void**)&cf,   g_cf);
    cudaGetSymbolAddress((void**)&sf,   g_sf);
    cudaGetSymbolAddress((void**)&attn, g_attn);

    const int B = BATCH, C = CCH, N = NSP;
    const long long CN = (long long)C * N;
    const long long NN = (long long)N * N;
    const long long WW = (long long)C * C;

    dim3 convGrid(N / 128, C / 128, B);   // (32,4,4)
    dim3 enGrid  (N / 128, N / 128, B);   // (32,32,4)
    dim3 chGrid  (C / 128, C / 128, B);   // (4,4,4)

    // ================= content self-attention =================
    mvn_kernel<<<B * C, 256>>>(content, xn, N);
    gemm_tc<<<convGrid, 256>>>(csa_w + 0 * WW, xn,      q, 0, C, 1, CN, N, 1, CN, csa_b + 0 * C, nullptr, 0, C, N, C);
    gemm_tc<<<convGrid, 256>>>(csa_w + 1 * WW, xn,      k, 0, C, 1, CN, N, 1, CN, csa_b + 1 * C, nullptr, 0, C, N, C);
    gemm_tc<<<convGrid, 256>>>(csa_w + 2 * WW, content, v, 0, C, 1, CN, N, 1, CN, csa_b + 2 * C, nullptr, 0, C, N, C);
    // E[i,j] = sum_c q[c,i] k[c,j]
    gemm_tc<<<enGrid, 256>>>(q, k, attn, CN, 1, N, CN, N, 1, NN, nullptr, nullptr, 0, N, N, C);
    softmax_kernel<<<B * N, 256>>>(attn, N);
    // O[c,i] = sum_j v[c,j] attn[i,j]
    gemm_tc<<<convGrid, 256>>>(v, attn, o, CN, N, 1, NN, 1, N, CN, nullptr, nullptr, 0, C, N, N);
    gemm_tc<<<convGrid, 256>>>(csa_w + 3 * WW, o, cf, 0, C, 1, CN, N, 1, CN, csa_b + 3 * C, content, CN, C, N, C);

    // ================= style self-attention (channel attention) =================
    mvn_kernel<<<B * C, 256>>>(style, xn, N);
    gemm_tc<<<convGrid, 256>>>(ssa_w + 0 * WW, style, q, 0, C, 1, CN, N, 1, CN, ssa_b + 0 * C, nullptr, 0, C, N, C); // f
    gemm_tc<<<convGrid, 256>>>(ssa_w + 1 * WW, style, k, 0, C, 1, CN, N, 1, CN, ssa_b + 1 * C, nullptr, 0, C, N, C); // g
    gemm_tc<<<convGrid, 256>>>(ssa_w + 2 * WW, xn,    v, 0, C, 1, CN, N, 1, CN, ssa_b + 2 * C, nullptr, 0, C, N, C); // h
    // E[c,d] = sum_i f[c,i] g[d,i]
    gemm_tc<<<chGrid, 256>>>(q, k, attn, CN, N, 1, CN, 1, N, WW, nullptr, nullptr, 0, C, C, N);
    softmax_kernel<<<B * C, 256>>>(attn, C);
    // O[c,i] = sum_d attn[d,c] h[d,i]
    gemm_tc<<<convGrid, 256>>>(attn, v, o, WW, 1, C, CN, N, 1, CN, nullptr, nullptr, 0, C, N, C);
    gemm_tc<<<convGrid, 256>>>(ssa_w + 3 * WW, o, sf, 0, C, 1, CN, N, 1, CN, ssa_b + 3 * C, style, CN, C, N, C);

    // ================= cross attention =================
    mvn_kernel<<<B * C, 256>>>(cf, xn, N);
    gemm_tc<<<convGrid, 256>>>(ca_w + 0 * WW, xn, q, 0, C, 1, CN, N, 1, CN, ca_b + 0 * C, nullptr, 0, C, N, C);
    mvn_kernel<<<B * C, 256>>>(sf, xn, N);
    gemm_tc<<<convGrid, 256>>>(ca_w + 1 * WW, xn, k, 0, C, 1, CN, N, 1, CN, ca_b + 1 * C, nullptr, 0, C, N, C);
    gemm_tc<<<convGrid, 256>>>(ca_w + 2 * WW, sf, v, 0, C, 1, CN, N, 1, CN, ca_b + 2 * C, nullptr, 0, C, N, C);
    gemm_tc<<<enGrid, 256>>>(q, k, attn, CN, 1, N, CN, N, 1, NN, nullptr, nullptr, 0, N, N, C);
    softmax_kernel<<<B * N, 256>>>(attn, N);
    gemm_tc<<<convGrid, 256>>>(v, attn, o, CN, N, 1, NN, 1, N, CN, nullptr, nullptr, 0, C, N, N);
    gemm_tc<<<convGrid, 256>>>(ca_w + 3 * WW, o, (float*)d_out, 0, C, 1, CN, N, 1, CN, ca_b + 3 * C, cf, CN, C, N, C);
}

// round 9
// speedup vs baseline: 1.4380x; 1.2723x over previous
#include <cuda_runtime.h>
#include <math.h>

#define EPSV 1e-5f

static const int BATCH = 4;
static const int CCH   = 512;
static const int NSP   = 4096;   // H*W

// ---------------- scratch (device globals; no runtime allocation) ----------------
__device__ float g_xn [(size_t)4 * 512 * 4096];
__device__ float g_q  [(size_t)4 * 512 * 4096];
__device__ float g_k  [(size_t)4 * 512 * 4096];
__device__ float g_v  [(size_t)4 * 512 * 4096];
__device__ float g_o  [(size_t)4 * 512 * 4096];   // also reused as split-K partials [4][8][512][512]
__device__ float g_cf [(size_t)4 * 512 * 4096];
__device__ float g_sf [(size_t)4 * 512 * 4096];
__device__ float g_attn[(size_t)4 * 4096 * 4096];

// ---------------- helpers ----------------
__device__ __forceinline__ unsigned f2tf(float x) {
    unsigned u;
    asm("cvt.rna.tf32.f32 %0, %1;" : "=r"(u) : "f"(x));
    return u;
}

__device__ __forceinline__ void mma8(float* c, const unsigned* a, const unsigned* b) {
    asm volatile(
        "mma.sync.aligned.m16n8k8.row.col.f32.tf32.tf32.f32 "
        "{%0,%1,%2,%3}, {%4,%5,%6,%7}, {%8,%9}, {%0,%1,%2,%3};"
        : "+f"(c[0]), "+f"(c[1]), "+f"(c[2]), "+f"(c[3])
        : "r"(a[0]), "r"(a[1]), "r"(a[2]), "r"(a[3]), "r"(b[0]), "r"(b[1]));
}

// ---------------- MVN: per-row mean/var normalize (unbiased var, ddof=1) ----------------
__global__ void mvn_kernel(const float* __restrict__ x, float* __restrict__ y, int n) {
    const float* xr = x + (size_t)blockIdx.x * n;
    float*       yr = y + (size_t)blockIdx.x * n;
    int tid = threadIdx.x;
    float s = 0.f, s2 = 0.f;
    for (int i = tid; i < n; i += blockDim.x) {
        float v = xr[i];
        s += v; s2 += v * v;
    }
    __shared__ float sh0[256];
    __shared__ float sh1[256];
    sh0[tid] = s; sh1[tid] = s2;
    __syncthreads();
    for (int o = 128; o > 0; o >>= 1) {
        if (tid < o) { sh0[tid] += sh0[tid + o]; sh1[tid] += sh1[tid + o]; }
        __syncthreads();
    }
    float mean = sh0[0] / (float)n;
    float var  = (sh1[0] - (float)n * mean * mean) / (float)(n - 1);
    float inv  = rsqrtf(var + EPSV);
    for (int i = tid; i < n; i += blockDim.x) {
        yr[i] = (xr[i] - mean) * inv;
    }
}

// ---------------- row softmax (in place), row cached in registers ----------------
__global__ void softmax_kernel(float* __restrict__ data, int n) {
    float* r = data + (size_t)blockIdx.x * n;
    int tid = threadIdx.x;
    int per = n / blockDim.x;       // 16 (spatial) or 2 (channel)
    float buf[16];
    __shared__ float sh[256];

    float m = -1e30f;
#pragma unroll 16
    for (int i = 0; i < 16; i++) {
        if (i < per) {
            float v = r[tid + i * blockDim.x];
            buf[i] = v;
            m = fmaxf(m, v);
        }
    }
    sh[tid] = m; __syncthreads();
    for (int o = 128; o > 0; o >>= 1) {
        if (tid < o) sh[tid] = fmaxf(sh[tid], sh[tid + o]);
        __syncthreads();
    }
    float mx = sh[0];
    __syncthreads();

    float s = 0.f;
#pragma unroll 16
    for (int i = 0; i < 16; i++) {
        if (i < per) {
            float e = __expf(buf[i] - mx);
            buf[i] = e;
            s += e;
        }
    }
    sh[tid] = s; __syncthreads();
    for (int o = 128; o > 0; o >>= 1) {
        if (tid < o) sh[tid] += sh[tid + o];
        __syncthreads();
    }
    float inv = 1.f / sh[0];
#pragma unroll 16
    for (int i = 0; i < 16; i++) {
        if (i < per) r[tid + i * blockDim.x] = buf[i] * inv;
    }
}

// ---------------- split-K partial reduction: out[b][i] = sum_kc part[b*8+kc][i] ----------------
__global__ void reduce8_kernel(const float* __restrict__ part, float* __restrict__ out) {
    const long long WWv = (long long)512 * 512 / 4;   // float4 elems per batch slice
    long long gid = (long long)blockIdx.x * blockDim.x + threadIdx.x;   // over B*WWv
    long long b = gid / WWv, i = gid % WWv;
    const float4* p = (const float4*)part + b * 8 * WWv + i;
    float4 a = p[0];
#pragma unroll
    for (int kc = 1; kc < 8; kc++) {
        float4 v = p[(long long)kc * WWv];
        a.x += v.x; a.y += v.y; a.z += v.z; a.w += v.w;
    }
    ((float4*)out)[b * WWv + i] = a;
}

// ---------------- TF32 tensor-core batched GEMM, generic strides (r3-proven) ----------------
// C[b][m][n] = sum_k A(m,k)*B(k,n) + bias[m] + res[b][m][n]
// nsplit>1: blockIdx.z = b*nsplit + kc; A/B advanced by kc*K along k; partial C
//   slab written at (b*nsplit+kc)*cBatch (no bias/res in that mode).
// Paired-k smem layout: As2[p][m] = float2( elem(k), elem(k+4) ),
//   p = ((k>>3)<<2) | (k&3),  component = (k>>2)&1.
// Requires M%128==0, N%128==0, K%16==0.
#define RS 132   // row stride in float2 units (128 + 4 pad)
__global__ __launch_bounds__(256) void gemm_tc(
    const float* __restrict__ A, const float* __restrict__ Bp, float* __restrict__ C,
    long long aBatch, long long sam, long long sak,
    long long bBatch, long long sbk, long long sbn,
    long long cBatch,
    const float* __restrict__ bias,
    const float* __restrict__ res, long long rBatch,
    int M, int N, int K, int nsplit)
{
    const int BM = 128, BK = 16;
    __shared__ float2 As2[8][RS];
    __shared__ float2 Bs2[8][RS];

    int bz = blockIdx.z;
    int kc = 0;
    if (nsplit > 1) { kc = bz % nsplit; bz /= nsplit; }
    A  += (long long)bz * aBatch + (long long)kc * K * sak;
    Bp += (long long)bz * bBatch + (long long)kc * K * sbk;
    C  += (long long)(bz * nsplit + kc) * cBatch;
    if (res) res += (long long)bz * rBatch;

    int tid  = threadIdx.x;
    int lane = tid & 31;
    int warp = tid >> 5;
    int m0 = blockIdx.y * BM;
    int n0 = blockIdx.x * BM;
    int wm = (warp & 1) * 64;   // 2 warps along M
    int wn = (warp >> 1) * 32;  // 4 warps along N

    bool aK = (sak == 1);
    bool bK = (sbk == 1);

    // per-thread global-load descriptors (8 elems per operand per tile)
    int a_kk, a_mm; long long aOff, aStep;
    if (aK) { a_kk = tid & 15; a_mm = tid >> 4;
              aOff = (long long)(m0 + a_mm) * sam + a_kk; aStep = 16 * sam; }
    else    { a_mm = tid & 127; a_kk = tid >> 7;
              aOff = (long long)(m0 + a_mm) * sam + (long long)a_kk * sak; aStep = 2 * sak; }
    int b_kk, b_nn; long long bOff, bStep;
    if (bK) { b_kk = tid & 15; b_nn = tid >> 4;
              bOff = (long long)(n0 + b_nn) * sbn + b_kk; bStep = 16 * sbn; }
    else    { b_nn = tid & 127; b_kk = tid >> 7;
              bOff = (long long)(n0 + b_nn) * sbn + (long long)b_kk * sbk; bStep = 2 * sbk; }

    // precomputed smem write targets
    int ap = ((a_kk >> 3) << 2) | (a_kk & 3);
    int ah = (a_kk >> 2) & 1;
    int bp = ((b_kk >> 3) << 2) | (b_kk & 3);
    int bh = (b_kk >> 2) & 1;

    // precomputed fragment read indices (float2 units)
    int r = lane >> 2;
    const unsigned aIdx = (unsigned)((lane & 3) * RS + wm + r);
    const unsigned bIdx = (unsigned)((lane & 3) * RS + wn + r);
    const float2* a2p = &As2[0][0];
    const float2* b2p = &Bs2[0][0];

    float acc[4][4][4];
#pragma unroll
    for (int mt = 0; mt < 4; mt++)
#pragma unroll
        for (int nt = 0; nt < 4; nt++)
#pragma unroll
            for (int i = 0; i < 4; i++) acc[mt][nt][i] = 0.f;

    float ra[8], rb[8];
#pragma unroll
    for (int i = 0; i < 8; i++) ra[i] = A[aOff + i * aStep];
#pragma unroll
    for (int i = 0; i < 8; i++) rb[i] = Bp[bOff + i * bStep];

    for (int k0 = 0; k0 < K; k0 += BK) {
        // stage registers -> smem (tf32, paired-k layout)
        if (aK) {
            unsigned* dst = (unsigned*)&As2[ap][a_mm] + ah;
#pragma unroll
            for (int i = 0; i < 8; i++) dst[32 * i] = f2tf(ra[i]);
        } else {
#pragma unroll
            for (int i = 0; i < 8; i++) {
                int k = a_kk + 2 * i;
                int p = ((k >> 3) << 2) | (k & 3);
                int h = (k >> 2) & 1;
                ((unsigned*)&As2[p][a_mm])[h] = f2tf(ra[i]);
            }
        }
        if (bK) {
            unsigned* dst = (unsigned*)&Bs2[bp][b_nn] + bh;
#pragma unroll
            for (int i = 0; i < 8; i++) dst[32 * i] = f2tf(rb[i]);
        } else {
#pragma unroll
            for (int i = 0; i < 8; i++) {
                int k = b_kk + 2 * i;
                int p = ((k >> 3) << 2) | (k & 3);
                int h = (k >> 2) & 1;
                ((unsigned*)&Bs2[p][b_nn])[h] = f2tf(rb[i]);
            }
        }
        __syncthreads();

        // prefetch next tile (in flight during compute)
        aOff += (long long)BK * sak;
        bOff += (long long)BK * sbk;
        if (k0 + BK < K) {
#pragma unroll
            for (int i = 0; i < 8; i++) ra[i] = A[aOff + i * aStep];
#pragma unroll
            for (int i = 0; i < 8; i++) rb[i] = Bp[bOff + i * bStep];
        }

        // compute 2 k-slices of 8 (slice ks uses rows p = 4*ks .. 4*ks+3)
#pragma unroll
        for (int ks = 0; ks < 2; ks++) {
            const unsigned off = ks * (4u * RS);
            unsigned af[4][4], bf[4][2];
#pragma unroll
            for (int mt = 0; mt < 4; mt++) {
                float2 lo = a2p[aIdx + off + mt * 16];
                float2 hi = a2p[aIdx + off + mt * 16 + 8];
                af[mt][0] = __float_as_uint(lo.x);
                af[mt][1] = __float_as_uint(hi.x);
                af[mt][2] = __float_as_uint(lo.y);
                af[mt][3] = __float_as_uint(hi.y);
            }
#pragma unroll
            for (int nt = 0; nt < 4; nt++) {
                float2 pb = b2p[bIdx + off + nt * 8];
                bf[nt][0] = __float_as_uint(pb.x);
                bf[nt][1] = __float_as_uint(pb.y);
            }
#pragma unroll
            for (int mt = 0; mt < 4; mt++)
#pragma unroll
                for (int nt = 0; nt < 4; nt++)
                    mma8(acc[mt][nt], af[mt], bf[nt]);
        }
        __syncthreads();
    }

    // epilogue: bias + residual, float2 stores
#pragma unroll
    for (int mt = 0; mt < 4; mt++) {
        int row = m0 + wm + mt * 16 + (lane >> 2);
        float bi0 = bias ? bias[row]     : 0.f;
        float bi1 = bias ? bias[row + 8] : 0.f;
#pragma unroll
        for (int nt = 0; nt < 4; nt++) {
            int col = n0 + wn + nt * 8 + 2 * (lane & 3);
            float2 v0 = make_float2(acc[mt][nt][0] + bi0, acc[mt][nt][1] + bi0);
            float2 v1 = make_float2(acc[mt][nt][2] + bi1, acc[mt][nt][3] + bi1);
            if (res) {
                float2 r0 = *(const float2*)(res + (long long)row * N + col);
                float2 r1 = *(const float2*)(res + (long long)(row + 8) * N + col);
                v0.x += r0.x; v0.y += r0.y;
                v1.x += r1.x; v1.y += r1.y;
            }
            *(float2*)(C + (long long)row * N + col)       = v0;
            *(float2*)(C + (long long)(row + 8) * N + col) = v1;
        }
    }
}

// ---------------- orchestration ----------------
extern "C" void kernel_launch(void* const* d_in, const int* in_sizes, int n_in,
                              void* d_out, int out_size) {
    const float* content = (const float*)d_in[0];
    const float* style   = (const float*)d_in[1];
    const float* csa_w   = (const float*)d_in[2];
    const float* csa_b   = (const float*)d_in[3];
    const float* ssa_w   = (const float*)d_in[4];
    const float* ssa_b   = (const float*)d_in[5];
    const float* ca_w    = (const float*)d_in[6];
    const float* ca_b    = (const float*)d_in[7];

    float *xn, *q, *k, *v, *o, *cf, *sf, *attn;
    cudaGetSymbolAddress((void**)&xn,   g_xn);
    cudaGetSymbolAddress((void**)&q,    g_q);
    cudaGetSymbolAddress((void**)&k,    g_k);
    cudaGetSymbolAddress((void**)&v,    g_v);
    cudaGetSymbolAddress((void**)&o,    g_o);
    cudaGetSymbolAddress((void**)&cf,   g_cf);
    cudaGetSymbolAddress((void**)&sf,   g_sf);
    cudaGetSymbolAddress((void**)&attn, g_attn);

    const int B = BATCH, C = CCH, N = NSP;
    const long long CN = (long long)C * N;
    const long long NN = (long long)N * N;
    const long long WW = (long long)C * C;

    dim3 convGrid(N / 128, C / 128, B);   // (32,4,4)
    dim3 enGrid  (N / 128, N / 128, B);   // (32,32,4)
    dim3 chSplitGrid(C / 128, C / 128, B * 8);   // (4,4,32) — split-K over spatial

    // ================= content self-attention =================
    mvn_kernel<<<B * C, 256>>>(content, xn, N);
    gemm_tc<<<convGrid, 256>>>(csa_w + 0 * WW, xn,      q, 0, C, 1, CN, N, 1, CN, csa_b + 0 * C, nullptr, 0, C, N, C, 1);
    gemm_tc<<<convGrid, 256>>>(csa_w + 1 * WW, xn,      k, 0, C, 1, CN, N, 1, CN, csa_b + 1 * C, nullptr, 0, C, N, C, 1);
    gemm_tc<<<convGrid, 256>>>(csa_w + 2 * WW, content, v, 0, C, 1, CN, N, 1, CN, csa_b + 2 * C, nullptr, 0, C, N, C, 1);
    // E[i,j] = sum_c q[c,i] k[c,j]
    gemm_tc<<<enGrid, 256>>>(q, k, attn, CN, 1, N, CN, N, 1, NN, nullptr, nullptr, 0, N, N, C, 1);
    softmax_kernel<<<B * N, 256>>>(attn, N);
    // O[c,i] = sum_j v[c,j] attn[i,j]
    gemm_tc<<<convGrid, 256>>>(v, attn, o, CN, N, 1, NN, 1, N, CN, nullptr, nullptr, 0, C, N, N, 1);
    gemm_tc<<<convGrid, 256>>>(csa_w + 3 * WW, o, cf, 0, C, 1, CN, N, 1, CN, csa_b + 3 * C, content, CN, C, N, C, 1);

    // ================= style self-attention (channel attention) =================
    mvn_kernel<<<B * C, 256>>>(style, xn, N);
    gemm_tc<<<convGrid, 256>>>(ssa_w + 0 * WW, style, q, 0, C, 1, CN, N, 1, CN, ssa_b + 0 * C, nullptr, 0, C, N, C, 1); // f
    gemm_tc<<<convGrid, 256>>>(ssa_w + 1 * WW, style, k, 0, C, 1, CN, N, 1, CN, ssa_b + 1 * C, nullptr, 0, C, N, C, 1); // g
    gemm_tc<<<convGrid, 256>>>(ssa_w + 2 * WW, xn,    v, 0, C, 1, CN, N, 1, CN, ssa_b + 2 * C, nullptr, 0, C, N, C, 1); // h
    // E[c,d] = sum_i f[c,i] g[d,i] — split-K x8: partials into g_o, reduce into attn
    gemm_tc<<<chSplitGrid, 256>>>(q, k, o, CN, N, 1, CN, 1, N, WW, nullptr, nullptr, 0, C, C, N / 8, 8);
    reduce8_kernel<<<(int)(B * WW / 4 / 256), 256>>>(o, attn);
    softmax_kernel<<<B * C, 256>>>(attn, C);
    // O[c,i] = sum_d attn[d,c] h[d,i]
    gemm_tc<<<convGrid, 256>>>(attn, v, o, WW, 1, C, CN, N, 1, CN, nullptr, nullptr, 0, C, N, C, 1);
    gemm_tc<<<convGrid, 256>>>(ssa_w + 3 * WW, o, sf, 0, C, 1, CN, N, 1, CN, ssa_b + 3 * C, style, CN, C, N, C, 1);

    // ================= cross attention =================
    mvn_kernel<<<B * C, 256>>>(cf, xn, N);
    gemm_tc<<<convGrid, 256>>>(ca_w + 0 * WW, xn, q, 0, C, 1, CN, N, 1, CN, ca_b + 0 * C, nullptr, 0, C, N, C, 1);
    mvn_kernel<<<B * C, 256>>>(sf, xn, N);
    gemm_tc<<<convGrid, 256>>>(ca_w + 1 * WW, xn, k, 0, C, 1, CN, N, 1, CN, ca_b + 1 * C, nullptr, 0, C, N, C, 1);
    gemm_tc<<<convGrid, 256>>>(ca_w + 2 * WW, sf, v, 0, C, 1, CN, N, 1, CN, ca_b + 2 * C, nullptr, 0, C, N, C, 1);
    gemm_tc<<<enGrid, 256>>>(q, k, attn, CN, 1, N, CN, N, 1, NN, nullptr, nullptr, 0, N, N, C, 1);
    softmax_kernel<<<B * N, 256>>>(attn, N);
    gemm_tc<<<convGrid, 256>>>(v, attn, o, CN, N, 1, NN, 1, N, CN, nullptr, nullptr, 0, C, N, N, 1);
    gemm_tc<<<convGrid, 256>>>(ca_w + 3 * WW, o, (float*)d_out, 0, C, 1, CN, N, 1, CN, ca_b + 3 * C, cf, CN, C, N, C, 1);
}